// round 9
// baseline (speedup 1.0000x reference)
#include <cuda_runtime.h>
#include <cuda_bf16.h>
#include <math.h>

#define BB 4096
#define LL 200
#define FF 8
#define DD 64
#define KK 15
// dynamic smem: per-row partials [200][8] float2 (each = dot/ssq over 8 floats)
#define SMEM_BYTES (LL * 8 * 8)   // 12800 B

__device__ __forceinline__ unsigned enc_f(float f) {
    unsigned u = __float_as_uint(f);
    return (u >> 31) ? ~u : (u ^ 0x80000000u);
}
__device__ __forceinline__ float dec_f(unsigned u) {
    unsigned bits = (u & 0x80000000u) ? (u ^ 0x80000000u) : ~u;
    return __uint_as_float(bits);
}

__global__ void __launch_bounds__(256, 6) search_predict_kernel(
    const int* __restrict__ x,        // [B, L, F] int32
    const int* __restrict__ self_loc, // [B] int32
    const float* __restrict__ E,      // [NFEAT+1, D] float32
    float* __restrict__ out)          // [B*16*8] x_out-as-float, then [B*15] sim_topk
{
    extern __shared__ __align__(16) float partials[];   // [200][8] float2, rot-swizzled

    __shared__ __align__(16) float4 selfv[16];          // self embedding row
    __shared__ int catS[LL];
    __shared__ __align__(16) unsigned long long keys[224];
    __shared__ __align__(16) unsigned simk[224];
    __shared__ unsigned long long selKey[KK];
    __shared__ int sortedL[KK + 1];
    __shared__ float invns;
    __shared__ int bad;

    const int b   = blockIdx.x;
    const int tid = threadIdx.x;
    const int warp = tid >> 5;

    const int* xb = x + (size_t)b * (LL * FF);
    const int sl = __ldg(self_loc + b);

    if (tid == 0) bad = 0;
    // catS by threads 0..199; warp 7 loads self row AND precomputes its inv-norm
    if (tid < LL) catS[tid] = __ldg(xb + tid * FF + 5);
    if (warp == 7) {
        const int hl = tid & 15;
        if ((tid & 31) < 16) {
            const int cs = __ldg(xb + sl * FF + 5);
            selfv[hl] = __ldg(reinterpret_cast<const float4*>(E + (size_t)cs * DD) + hl);
        }
        __syncwarp();
        const float4 s = selfv[hl];                       // lanes 16-31 mirror 0-15
        float q = s.x * s.x + s.y * s.y + s.z * s.z + s.w * s.w;
        q += __shfl_xor_sync(0xffffffffu, q, 8);
        q += __shfl_xor_sync(0xffffffffu, q, 4);
        q += __shfl_xor_sync(0xffffffffu, q, 2);
        q += __shfl_xor_sync(0xffffffffu, q, 1);
        if (tid == 224) invns = rsqrtf(q + 1e-8f);
    }
    __syncthreads();

    // ---- Phase A: fused gather + partials, rows l <= sl, 2 rows/thread-iter (MLP=4)
    {
        const int rg = tid >> 3;          // row within 32-row tile
        const int j8 = tid & 7;           // owns float4 slices j8 and j8+8
        const float4 sa = selfv[j8];
        const float4 sb = selfv[j8 + 8];

        #pragma unroll
        for (int itp = 0; itp < 3; ++itp) {               // pairs: rows it*32 and it*32+32
            const int l0 = itp * 64 + rg;
            const int l1 = l0 + 32;
            const bool p0 = (l0 <= sl), p1 = (l1 <= sl);
            float4 va0, vb0, va1, vb1;
            if (p0) {                     // all four loads issued before any FMA
                const float4* rp = reinterpret_cast<const float4*>(E + (size_t)catS[l0] * DD);
                va0 = __ldg(rp + j8);
                vb0 = __ldg(rp + j8 + 8);
            }
            if (p1) {
                const float4* rp = reinterpret_cast<const float4*>(E + (size_t)catS[l1] * DD);
                va1 = __ldg(rp + j8);
                vb1 = __ldg(rp + j8 + 8);
            }
            if (p0) {
                const float dp = va0.x*sa.x + va0.y*sa.y + va0.z*sa.z + va0.w*sa.w
                               + vb0.x*sb.x + vb0.y*sb.y + vb0.z*sb.z + vb0.w*sb.w;
                const float qp = va0.x*va0.x + va0.y*va0.y + va0.z*va0.z + va0.w*va0.w
                               + vb0.x*vb0.x + vb0.y*vb0.y + vb0.z*vb0.z + vb0.w*vb0.w;
                const int byteoff = l0 * 64 + ((((j8 >> 1) + (l0 >> 1)) & 3) << 4)
                                  + ((j8 & 1) << 3);
                *reinterpret_cast<float2*>(reinterpret_cast<char*>(partials) + byteoff)
                    = make_float2(dp, qp);
            }
            if (p1) {
                const float dp = va1.x*sa.x + va1.y*sa.y + va1.z*sa.z + va1.w*sa.w
                               + vb1.x*sb.x + vb1.y*sb.y + vb1.z*sb.z + vb1.w*sb.w;
                const float qp = va1.x*va1.x + va1.y*va1.y + va1.z*va1.z + va1.w*va1.w
                               + vb1.x*vb1.x + vb1.y*vb1.y + vb1.z*vb1.z + vb1.w*vb1.w;
                const int byteoff = l1 * 64 + ((((j8 >> 1) + (l1 >> 1)) & 3) << 4)
                                  + ((j8 & 1) << 3);
                *reinterpret_cast<float2*>(reinterpret_cast<char*>(partials) + byteoff)
                    = make_float2(dp, qp);
            }
        }
        {   // tail: row 192 + rg (l in [192, 224))
            const int l = 192 + rg;
            if (l <= sl && l < LL) {
                const float4* rp = reinterpret_cast<const float4*>(E + (size_t)catS[l] * DD);
                const float4 va = __ldg(rp + j8);
                const float4 vb = __ldg(rp + j8 + 8);
                const float dp = va.x*sa.x + va.y*sa.y + va.z*sa.z + va.w*sa.w
                               + vb.x*sb.x + vb.y*sb.y + vb.z*sb.z + vb.w*sb.w;
                const float qp = va.x*va.x + va.y*va.y + va.z*va.z + va.w*va.w
                               + vb.x*vb.x + vb.y*vb.y + vb.z*vb.z + vb.w*vb.w;
                const int byteoff = l * 64 + ((((j8 >> 1) + (l >> 1)) & 3) << 4)
                                  + ((j8 & 1) << 3);
                *reinterpret_cast<float2*>(reinterpret_cast<char*>(partials) + byteoff)
                    = make_float2(dp, qp);
            }
        }
    }
    __syncthreads();

    // ---- Phase B: thread-per-row reduction, only rows <= sl ----
    float dot = 0.f, ssq = 0.f;
    if (tid <= sl) {
        const char* base = reinterpret_cast<const char*>(partials) + tid * 64;
        const int rot = (tid >> 1) & 3;
        #pragma unroll
        for (int k = 0; k < 4; ++k) {     // logical chunk order fixed (bit-exact dups)
            const float4 c = *reinterpret_cast<const float4*>(base + (((k + rot) & 3) << 4));
            dot += c.x + c.z;
            ssq += c.y + c.w;
        }
    }
    const float sim = (tid < sl) ? dot * rsqrtf(ssq + 1e-8f) * invns : -2.0f;
    const unsigned e = enc_f(sim);
    const unsigned long long myKey =
        ((unsigned long long)e << 32) | (unsigned)(LL - 1 - tid);
    if (tid < 224) { keys[tid] = myKey; simk[tid] = e; }   // 200..223 pad, inert
    __syncthreads();

    // ---- rank-select among the first sl keys only ----
    int rank = LL;
    if (tid < sl) {
        int r = 0;
        const uint4* p = reinterpret_cast<const uint4*>(simk);
        const int nj = (sl + 3) >> 2;
        for (int j = 0; j < nj; ++j) {            // broadcast LDS.128
            const uint4 k = p[j];
            r += (k.x > e);
            r += (k.y > e);
            r += (k.z > e);
            r += (k.w > e);
        }
        rank = r;
        if (r < KK) selKey[r] = myKey;
    }
    __syncthreads();

    // tie inside top-K -> two threads shared a slot -> loser flags; rare
    if (rank < KK && selKey[rank] != myKey) bad = 1;
    __syncthreads();

    if (bad) {   // exact 64-bit tie-aware recount (keys strictly unique)
        if (tid < sl) {
            int r2 = 0;
            const ulonglong2* k2 = reinterpret_cast<const ulonglong2*>(keys);
            const int nj2 = (sl + 1) >> 1;
            for (int j = 0; j < nj2; ++j) {
                const ulonglong2 kk = k2[j];
                r2 += (kk.x > myKey);
                r2 += (kk.y > myKey);
            }
            if (r2 < KK) selKey[r2] = myKey;
        }
        __syncthreads();
    }

    // ---- sort the 15 selected by ascending index; emit sim_topk ----
    if (tid < KK) {
        const unsigned long long mk = selKey[tid];
        const unsigned myLow = (unsigned)mk;        // 199 - l (larger = smaller l)
        int pos = 0;
        #pragma unroll
        for (int j = 0; j < KK; ++j) pos += ((unsigned)selKey[j] > myLow);
        const int l = LL - 1 - (int)myLow;
        sortedL[pos] = l;
        out[(size_t)BB * ((KK + 1) * FF) + (size_t)b * KK + pos] = dec_f((unsigned)(mk >> 32));
    }
    if (tid == KK) sortedL[KK] = sl;
    __syncthreads();

    // ---- x_out: [16 rows x 8 feats] as float ----
    if (tid < (KK + 1) * FF) {
        const int r = tid >> 3;
        const int f = tid & 7;
        const int l = sortedL[r];
        out[(size_t)b * ((KK + 1) * FF) + tid] = (float)__ldg(xb + l * FF + f);
    }
}

extern "C" void kernel_launch(void* const* d_in, const int* in_sizes, int n_in,
                              void* d_out, int out_size) {
    const int*   x  = (const int*)d_in[0];   // x: [4096, 200, 8] int32
    const int*   sl = (const int*)d_in[1];   // self_loc: [4096] int32
    const float* E  = (const float*)d_in[2]; // E: [100001, 64] float32
    float* out = (float*)d_out;

    search_predict_kernel<<<BB, 256, SMEM_BYTES>>>(x, sl, E, out);
}